// round 1
// baseline (speedup 1.0000x reference)
#include <cuda_runtime.h>
#include <cuda_bf16.h>
#include <math.h>

#define Bsz 32
#define Lsz 512
#define Dm  288
#define D3  864
#define Hh  8
#define HD  36
#define Vv  4096
#define TOK (Bsz*Lsz)   // 16384

// ---------------- scratch (device globals; no allocations allowed) ----------
__device__ float g_h [TOK*Dm];
__device__ float g_xn[TOK*Dm];
__device__ float g_a [TOK*D3];
__device__ float g_b [TOK*D3];
__device__ float g_t [TOK*Dm];
__device__ float g_kt[Bsz*Hh*HD*Lsz];
__device__ float g_vt[Bsz*Hh*HD*Lsz];

// ---------------- embedding ------------------------------------------------
__global__ void embed_k(const int* __restrict__ x, const float* __restrict__ emb,
                        const float* __restrict__ pos, float* __restrict__ h)
{
    int t = blockIdx.x;          // token 0..16383
    int d = threadIdx.x;         // 0..287
    int tok = x[t];
    int l = t & (Lsz-1);
    h[(size_t)t*Dm + d] = emb[(size_t)tok*Dm + d] + pos[(size_t)l*Dm + d];
}

// ---------------- rmsnorm (warp per token) ----------------------------------
__global__ void rmsnorm_k(const float* __restrict__ x, const float* __restrict__ scale,
                          float* __restrict__ y)
{
    int gw   = (blockIdx.x*blockDim.x + threadIdx.x) >> 5;
    int lane = threadIdx.x & 31;
    if (gw >= TOK) return;
    const float* xr = x + (size_t)gw*Dm;
    float v[9];
    float ss = 0.f;
#pragma unroll
    for (int j = 0; j < 9; j++) { v[j] = xr[lane + 32*j]; ss += v[j]*v[j]; }
#pragma unroll
    for (int off = 16; off; off >>= 1) ss += __shfl_xor_sync(~0u, ss, off);
    float norm = sqrtf(ss * (1.f/Dm));
    float inv  = 1.f / (norm + 1e-6f);
    float* yr = y + (size_t)gw*Dm;
#pragma unroll
    for (int j = 0; j < 9; j++) yr[lane + 32*j] = scale[lane + 32*j] * v[j] * inv;
}

// ---------------- GEMM: C[M,N] = A[M,K] * B[N,K]^T (+ residual) -------------
// 64x64 tile, BK=16, 256 threads, 4x4 per thread. M%64==0, K%16==0, N%4==0.
__global__ void gemm_k(const float* __restrict__ A, const float* __restrict__ B,
                       const float* __restrict__ R, float* __restrict__ C,
                       int M, int N, int K, int addRes)
{
    __shared__ float As[16][64];
    __shared__ float Bs[16][64];
    int tx = threadIdx.x, ty = threadIdx.y;
    int tid = ty*16 + tx;
    int n0 = blockIdx.x*64, m0 = blockIdx.y*64;
    float acc[4][4] = {};
    int row  = tid >> 2;          // 0..63
    int kcol = (tid & 3) * 4;     // 0,4,8,12

    for (int k0 = 0; k0 < K; k0 += 16) {
        float4 av = *(const float4*)(A + (size_t)(m0+row)*K + k0 + kcol);
        As[kcol+0][row] = av.x; As[kcol+1][row] = av.y;
        As[kcol+2][row] = av.z; As[kcol+3][row] = av.w;
        float4 bv = make_float4(0.f,0.f,0.f,0.f);
        if (n0 + row < N)
            bv = *(const float4*)(B + (size_t)(n0+row)*K + k0 + kcol);
        Bs[kcol+0][row] = bv.x; Bs[kcol+1][row] = bv.y;
        Bs[kcol+2][row] = bv.z; Bs[kcol+3][row] = bv.w;
        __syncthreads();
#pragma unroll
        for (int kk = 0; kk < 16; kk++) {
            float4 a = *(const float4*)&As[kk][ty*4];
            float4 b = *(const float4*)&Bs[kk][tx*4];
            acc[0][0] += a.x*b.x; acc[0][1] += a.x*b.y; acc[0][2] += a.x*b.z; acc[0][3] += a.x*b.w;
            acc[1][0] += a.y*b.x; acc[1][1] += a.y*b.y; acc[1][2] += a.y*b.z; acc[1][3] += a.y*b.w;
            acc[2][0] += a.z*b.x; acc[2][1] += a.z*b.y; acc[2][2] += a.z*b.z; acc[2][3] += a.z*b.w;
            acc[3][0] += a.w*b.x; acc[3][1] += a.w*b.y; acc[3][2] += a.w*b.z; acc[3][3] += a.w*b.w;
        }
        __syncthreads();
    }
    int n = n0 + tx*4;
    if (n < N) {
#pragma unroll
        for (int i = 0; i < 4; i++) {
            size_t off = (size_t)(m0 + ty*4 + i)*N + n;
            float4 v = make_float4(acc[i][0], acc[i][1], acc[i][2], acc[i][3]);
            if (addRes) {
                float4 r = *(const float4*)(R + off);
                v.x += r.x; v.y += r.y; v.z += r.z; v.w += r.w;
            }
            *(float4*)(C + off) = v;
        }
    }
}

// ---------------- K/V transpose to [bh][d][l] --------------------------------
__global__ void kvt_k(const float* __restrict__ qkv, float* __restrict__ kt,
                      float* __restrict__ vt)
{
    int idx = blockIdx.x*blockDim.x + threadIdx.x;
    if (idx >= Bsz*Hh*HD*Lsz) return;
    int d  = idx % HD;
    int l  = (idx / HD) & (Lsz-1);
    int bh = idx / (HD*Lsz);
    int b = bh >> 3, h = bh & 7;
    size_t src = (size_t)(b*Lsz + l)*D3 + h*HD + d;
    size_t dst = ((size_t)bh*HD + d)*Lsz + l;
    kt[dst] = qkv[src + Dm];
    vt[dst] = qkv[src + 2*Dm];
}

// ---------------- attention: warp per (b,h,q), online softmax ---------------
__global__ void attn_k(const float* __restrict__ qkv, const float* __restrict__ kt,
                       const float* __restrict__ vt, float* __restrict__ out)
{
    int wid  = threadIdx.x >> 5;
    int lane = threadIdx.x & 31;
    int bh = blockIdx.x >> 6;                 // 0..255
    int q  = ((blockIdx.x & 63) << 3) + wid;  // 0..511
    int b = bh >> 3, h = bh & 7;

    const float* qrow = qkv + (size_t)(b*Lsz + q)*D3 + h*HD;
    float qv[HD];
#pragma unroll
    for (int d = 0; d < HD; d++) qv[d] = qrow[d] * (1.f/6.f);

    const float* ktb = kt + (size_t)bh*HD*Lsz;
    const float* vtb = vt + (size_t)bh*HD*Lsz;

    float m = -1e30f, ssum = 0.f;
    float o[HD];
#pragma unroll
    for (int d = 0; d < HD; d++) o[d] = 0.f;

    int nch = (q >> 5) + 1;
    for (int c = 0; c < nch; c++) {
        int k = (c << 5) + lane;
        float s = -1e30f;
        if (k <= q) {
            float acc = 0.f;
#pragma unroll
            for (int d = 0; d < HD; d++) acc += qv[d] * ktb[d*Lsz + k];
            s = acc;
        }
        float cm = s;
#pragma unroll
        for (int off = 16; off; off >>= 1) cm = fmaxf(cm, __shfl_xor_sync(~0u, cm, off));
        float nm = fmaxf(m, cm);
        float alpha = __expf(m - nm);
        float p = (k <= q) ? __expf(s - nm) : 0.f;
        float ps = p;
#pragma unroll
        for (int off = 16; off; off >>= 1) ps += __shfl_xor_sync(~0u, ps, off);
        ssum = ssum*alpha + ps;
#pragma unroll
        for (int d = 0; d < HD; d++) o[d] = o[d]*alpha + p * vtb[d*Lsz + k];
        m = nm;
    }
#pragma unroll
    for (int d = 0; d < HD; d++) {
#pragma unroll
        for (int off = 16; off; off >>= 1) o[d] += __shfl_xor_sync(~0u, o[d], off);
    }
    if (lane == 0) {
        float inv = 1.f/ssum;
        float* orow = out + (size_t)(b*Lsz + q)*Dm + h*HD;
#pragma unroll
        for (int d = 0; d < HD; d++) orow[d] = o[d]*inv;
    }
}

// ---------------- linear recurrence scan -------------------------------------
__global__ void scan_k(const float* __restrict__ gvf, float* __restrict__ out)
{
    int idx = blockIdx.x*blockDim.x + threadIdx.x;
    if (idx >= Bsz*Dm) return;
    int b = idx / Dm, d = idx % Dm;
    const float* base = gvf + (size_t)b*Lsz*D3;
    float h = 0.f;
    for (int l = 0; l < Lsz; l++) {
        const float* r = base + (size_t)l*D3;
        float g = r[d], v = r[Dm + d], f = r[2*Dm + d];
        float ft = 1.f / (1.f + __expf(1.f - f));   // sigmoid(f - 1)
        h = ft*h + (1.f - ft)*v;
        float gs = 1.f / (1.f + __expf(-g));
        out[(size_t)(b*Lsz + l)*Dm + d] = gs * h;
    }
}

// ---------------- silu(gate) * up (in place into gate) ----------------------
__global__ void silu_mul_k(float* __restrict__ g, const float* __restrict__ u, int n)
{
    int i = blockIdx.x*blockDim.x + threadIdx.x;
    if (i < n) {
        float x = g[i];
        g[i] = (x / (1.f + __expf(-x))) * u[i];
    }
}

// ---------------- host orchestration ----------------------------------------
static inline void run_gemm(const float* A, const float* B, const float* R,
                            float* C, int M, int N, int K, int addRes)
{
    dim3 grid((N + 63)/64, M/64);
    dim3 blk(16, 16);
    gemm_k<<<grid, blk>>>(A, B, R, C, M, N, K, addRes);
}

extern "C" void kernel_launch(void* const* d_in, const int* in_sizes, int n_in,
                              void* d_out, int out_size)
{
    const int*   x         = (const int*)  d_in[0];
    const float* emb       = (const float*)d_in[1];
    const float* pos_emb   = (const float*)d_in[2];
    const float* attn_qkv  = (const float*)d_in[3];
    const float* attn_out  = (const float*)d_in[4];
    const float* attn_norm = (const float*)d_in[5];
    const float* rec_in    = (const float*)d_in[6];
    const float* rec_out   = (const float*)d_in[7];
    const float* rec_norm  = (const float*)d_in[8];
    const float* ffn_gate  = (const float*)d_in[9];
    const float* ffn_up    = (const float*)d_in[10];
    const float* ffn_down  = (const float*)d_in[11];
    const float* ffn_norm  = (const float*)d_in[12];
    const float* final_nrm = (const float*)d_in[13];
    float* out = (float*)d_out;

    float *ph, *pxn, *pa, *pb, *pt, *pkt, *pvt;
    cudaGetSymbolAddress((void**)&ph,  g_h);
    cudaGetSymbolAddress((void**)&pxn, g_xn);
    cudaGetSymbolAddress((void**)&pa,  g_a);
    cudaGetSymbolAddress((void**)&pb,  g_b);
    cudaGetSymbolAddress((void**)&pt,  g_t);
    cudaGetSymbolAddress((void**)&pkt, g_kt);
    cudaGetSymbolAddress((void**)&pvt, g_vt);

    const int rms_blocks = (TOK*32 + 255)/256;

    embed_k<<<TOK, Dm>>>(x, emb, pos_emb, ph);

    int ai = 0, ri = 0;
    for (int i = 0; i < 14; i++) {
        bool is_attn = ((i + 1) % 3 == 0);
        if (is_attn) {
            rmsnorm_k<<<rms_blocks, 256>>>(ph, attn_norm + (size_t)ai*Dm, pxn);
            run_gemm(pxn, attn_qkv + (size_t)ai*D3*Dm, nullptr, pa, TOK, D3, Dm, 0);
            kvt_k<<<(Bsz*Hh*HD*Lsz + 255)/256, 256>>>(pa, pkt, pvt);
            attn_k<<<Bsz*Hh*64, 256>>>(pa, pkt, pvt, pt);
            run_gemm(pt, attn_out + (size_t)ai*Dm*Dm, ph, ph, TOK, Dm, Dm, 1);
            ai++;
        } else {
            rmsnorm_k<<<rms_blocks, 256>>>(ph, rec_norm + (size_t)ri*Dm, pxn);
            run_gemm(pxn, rec_in + (size_t)ri*D3*Dm, nullptr, pa, TOK, D3, Dm, 0);
            scan_k<<<(Bsz*Dm + 255)/256, 256>>>(pa, pt);
            run_gemm(pt, rec_out + (size_t)ri*Dm*Dm, ph, ph, TOK, Dm, Dm, 1);
            ri++;
        }
        // FFN
        rmsnorm_k<<<rms_blocks, 256>>>(ph, ffn_norm + (size_t)i*Dm, pxn);
        run_gemm(pxn, ffn_gate + (size_t)i*D3*Dm, nullptr, pa, TOK, D3, Dm, 0);
        run_gemm(pxn, ffn_up   + (size_t)i*D3*Dm, nullptr, pb, TOK, D3, Dm, 0);
        silu_mul_k<<<(TOK*D3 + 255)/256, 256>>>(pa, pb, TOK*D3);
        run_gemm(pa, ffn_down + (size_t)i*Dm*D3, ph, ph, TOK, Dm, D3, 1);
    }

    rmsnorm_k<<<rms_blocks, 256>>>(ph, final_nrm, pxn);
    run_gemm(pxn, emb, nullptr, out, TOK, Vv, Dm, 0);
}

// round 3
// speedup vs baseline: 1.7405x; 1.7405x over previous
#include <cuda_runtime.h>
#include <cuda_bf16.h>
#include <mma.h>
#include <math.h>

using namespace nvcuda;

#define Bsz 32
#define Lsz 512
#define Dm  288
#define D3  864
#define Hh  8
#define HD  36
#define Vv  4096
#define TOK (Bsz*Lsz)   // 16384

#define NCH 16
#define CHL (Lsz/NCH)   // 32

// ---------------- scratch (device globals; no allocations allowed) ----------
__device__ float g_h [TOK*Dm];
__device__ float g_xn[TOK*Dm];
__device__ float g_a [TOK*D3];
__device__ float g_b [TOK*D3];
__device__ float g_t [TOK*Dm];
__device__ float g_kt[Bsz*Hh*HD*Lsz];
__device__ float g_vt[Bsz*Hh*HD*Lsz];
__device__ float g_ca[Bsz*NCH*Dm];
__device__ float g_ch[Bsz*NCH*Dm];

// ---------------- embedding ------------------------------------------------
__global__ void embed_k(const int* __restrict__ x, const float* __restrict__ emb,
                        const float* __restrict__ pos, float* __restrict__ h)
{
    int t = blockIdx.x;
    int d = threadIdx.x;
    int tok = x[t];
    int l = t & (Lsz-1);
    h[(size_t)t*Dm + d] = emb[(size_t)tok*Dm + d] + pos[(size_t)l*Dm + d];
}

// ---------------- rmsnorm (warp per token) ----------------------------------
__global__ void rmsnorm_k(const float* __restrict__ x, const float* __restrict__ scale,
                          float* __restrict__ y)
{
    int gw   = (blockIdx.x*blockDim.x + threadIdx.x) >> 5;
    int lane = threadIdx.x & 31;
    if (gw >= TOK) return;
    const float* xr = x + (size_t)gw*Dm;
    float v[9];
    float ss = 0.f;
#pragma unroll
    for (int j = 0; j < 9; j++) { v[j] = xr[lane + 32*j]; ss += v[j]*v[j]; }
#pragma unroll
    for (int off = 16; off; off >>= 1) ss += __shfl_xor_sync(~0u, ss, off);
    float norm = sqrtf(ss * (1.f/Dm));
    float inv  = 1.f / (norm + 1e-6f);
    float* yr = y + (size_t)gw*Dm;
#pragma unroll
    for (int j = 0; j < 9; j++) yr[lane + 32*j] = scale[lane + 32*j] * v[j] * inv;
}

// ---------------- bf16x3 tensor-core GEMM ------------------------------------
// C[M,N] = A[M,K] * B[N,K]^T (+R), emulated fp32 via hi/lo bf16 split:
//   C ≈ Ah*Bh + Ah*Bl + Al*Bh  (fp32 accumulate)
// BM=128, BN=64, BK=32. 256 thr, 8 warps (4m x 2n), warp tile 32x32 via
// 2x2 wmma m16n16k16 fragments. Requirements: M%128==0, K%32==0, N%16==0.
#define GBM 128
#define GBN 64
#define GBK 32
#define GLDS 40   // bf16 elems; 80B row pitch (16B-aligned)

__global__ void gemm_tc_k(const float* __restrict__ A, const float* __restrict__ B,
                          const float* __restrict__ R, float* __restrict__ C,
                          int M, int N, int K, int addRes)
{
    __shared__ __align__(32) __nv_bfloat16 Ah[GBM][GLDS];
    __shared__ __align__(32) __nv_bfloat16 Al[GBM][GLDS];
    __shared__ __align__(32) __nv_bfloat16 Bh[GBN][GLDS];
    __shared__ __align__(32) __nv_bfloat16 Bl[GBN][GLDS];

    int tid = threadIdx.x;
    int wid = tid >> 5;
    int wm  = wid & 3;     // 0..3
    int wn  = wid >> 2;    // 0..1
    int m0  = blockIdx.y*GBM;
    int n0  = blockIdx.x*GBN;

    wmma::fragment<wmma::accumulator,16,16,16,float> acc[2][2];
#pragma unroll
    for (int i = 0; i < 2; i++)
#pragma unroll
        for (int j = 0; j < 2; j++)
            wmma::fill_fragment(acc[i][j], 0.f);

    for (int k0 = 0; k0 < K; k0 += GBK) {
        // A tile: 128x32 floats = 1024 float4, 4 per thread
#pragma unroll
        for (int t = 0; t < 4; t++) {
            int idx = tid + t*256;
            int row = idx >> 3;
            int kq  = (idx & 7) << 2;
            float4 v = *(const float4*)(A + (size_t)(m0+row)*K + k0 + kq);
            float fv[4] = {v.x, v.y, v.z, v.w};
#pragma unroll
            for (int j = 0; j < 4; j++) {
                __nv_bfloat16 hi = __float2bfloat16_rn(fv[j]);
                Ah[row][kq+j] = hi;
                Al[row][kq+j] = __float2bfloat16_rn(fv[j] - __bfloat162float(hi));
            }
        }
        // B tile: 64x32 floats = 512 float4, 2 per thread (guard N)
#pragma unroll
        for (int t = 0; t < 2; t++) {
            int idx = tid + t*256;
            int row = idx >> 3;
            int kq  = (idx & 7) << 2;
            float4 v = make_float4(0.f,0.f,0.f,0.f);
            if (n0 + row < N)
                v = *(const float4*)(B + (size_t)(n0+row)*K + k0 + kq);
            float fv[4] = {v.x, v.y, v.z, v.w};
#pragma unroll
            for (int j = 0; j < 4; j++) {
                __nv_bfloat16 hi = __float2bfloat16_rn(fv[j]);
                Bh[row][kq+j] = hi;
                Bl[row][kq+j] = __float2bfloat16_rn(fv[j] - __bfloat162float(hi));
            }
        }
        __syncthreads();

#pragma unroll
        for (int kk = 0; kk < GBK; kk += 16) {
            wmma::fragment<wmma::matrix_a,16,16,16,__nv_bfloat16,wmma::row_major> ah[2], al[2];
            wmma::fragment<wmma::matrix_b,16,16,16,__nv_bfloat16,wmma::col_major> bh[2], bl[2];
#pragma unroll
            for (int i = 0; i < 2; i++) {
                wmma::load_matrix_sync(ah[i], &Ah[wm*32 + i*16][kk], GLDS);
                wmma::load_matrix_sync(al[i], &Al[wm*32 + i*16][kk], GLDS);
            }
#pragma unroll
            for (int j = 0; j < 2; j++) {
                wmma::load_matrix_sync(bh[j], &Bh[wn*32 + j*16][kk], GLDS);
                wmma::load_matrix_sync(bl[j], &Bl[wn*32 + j*16][kk], GLDS);
            }
#pragma unroll
            for (int i = 0; i < 2; i++)
#pragma unroll
                for (int j = 0; j < 2; j++) {
                    wmma::mma_sync(acc[i][j], ah[i], bh[j], acc[i][j]);
                    wmma::mma_sync(acc[i][j], ah[i], bl[j], acc[i][j]);
                    wmma::mma_sync(acc[i][j], al[i], bh[j], acc[i][j]);
                }
        }
        __syncthreads();
    }

#pragma unroll
    for (int i = 0; i < 2; i++) {
#pragma unroll
        for (int j = 0; j < 2; j++) {
            int nb = n0 + wn*32 + j*16;
            if (nb >= N) continue;
            size_t off = (size_t)(m0 + wm*32 + i*16)*N + nb;
            if (addRes) {
                wmma::fragment<wmma::accumulator,16,16,16,float> rf;
                wmma::load_matrix_sync(rf, R + off, N, wmma::mem_row_major);
#pragma unroll
                for (int e = 0; e < rf.num_elements; e++)
                    acc[i][j].x[e] += rf.x[e];
            }
            wmma::store_matrix_sync(C + off, acc[i][j], N, wmma::mem_row_major);
        }
    }
}

// ---------------- K/V transpose to [bh][d][l] --------------------------------
__global__ void kvt_k(const float* __restrict__ qkv, float* __restrict__ kt,
                      float* __restrict__ vt)
{
    int idx = blockIdx.x*blockDim.x + threadIdx.x;
    if (idx >= Bsz*Hh*HD*Lsz) return;
    int d  = idx % HD;
    int l  = (idx / HD) & (Lsz-1);
    int bh = idx / (HD*Lsz);
    int b = bh >> 3, h = bh & 7;
    size_t src = (size_t)(b*Lsz + l)*D3 + h*HD + d;
    size_t dst = ((size_t)bh*HD + d)*Lsz + l;
    kt[dst] = qkv[src + Dm];
    vt[dst] = qkv[src + 2*Dm];
}

// ---------------- attention: warp per (b,h,q), online softmax ---------------
__global__ void attn_k(const float* __restrict__ qkv, const float* __restrict__ kt,
                       const float* __restrict__ vt, float* __restrict__ out)
{
    int wid  = threadIdx.x >> 5;
    int lane = threadIdx.x & 31;
    int bh = blockIdx.x >> 6;
    int q  = ((blockIdx.x & 63) << 3) + wid;
    int b = bh >> 3, h = bh & 7;

    const float* qrow = qkv + (size_t)(b*Lsz + q)*D3 + h*HD;
    float qv[HD];
#pragma unroll
    for (int d = 0; d < HD; d++) qv[d] = qrow[d] * (1.f/6.f);

    const float* ktb = kt + (size_t)bh*HD*Lsz;
    const float* vtb = vt + (size_t)bh*HD*Lsz;

    float m = -1e30f, ssum = 0.f;
    float o[HD];
#pragma unroll
    for (int d = 0; d < HD; d++) o[d] = 0.f;

    int nch = (q >> 5) + 1;
    for (int c = 0; c < nch; c++) {
        int k = (c << 5) + lane;
        float s = -1e30f;
        if (k <= q) {
            float acc = 0.f;
#pragma unroll
            for (int d = 0; d < HD; d++) acc += qv[d] * ktb[d*Lsz + k];
            s = acc;
        }
        float cm = s;
#pragma unroll
        for (int off = 16; off; off >>= 1) cm = fmaxf(cm, __shfl_xor_sync(~0u, cm, off));
        float nm = fmaxf(m, cm);
        float alpha = __expf(m - nm);
        float p = (k <= q) ? __expf(s - nm) : 0.f;
        float ps = p;
#pragma unroll
        for (int off = 16; off; off >>= 1) ps += __shfl_xor_sync(~0u, ps, off);
        ssum = ssum*alpha + ps;
#pragma unroll
        for (int d = 0; d < HD; d++) o[d] = o[d]*alpha + p * vtb[d*Lsz + k];
        m = nm;
    }
#pragma unroll
    for (int d = 0; d < HD; d++) {
#pragma unroll
        for (int off = 16; off; off >>= 1) o[d] += __shfl_xor_sync(~0u, o[d], off);
    }
    if (lane == 0) {
        float inv = 1.f/ssum;
        float* orow = out + (size_t)(b*Lsz + q)*Dm + h*HD;
#pragma unroll
        for (int d = 0; d < HD; d++) orow[d] = o[d]*inv;
    }
}

// ---------------- parallel linear recurrence scan (3 passes) -----------------
__global__ void scan1_k(const float* __restrict__ gvf,
                        float* __restrict__ ca, float* __restrict__ ch)
{
    int idx = blockIdx.x*blockDim.x + threadIdx.x;
    if (idx >= Bsz*NCH*Dm) return;
    int d = idx % Dm;
    int c = (idx / Dm) % NCH;
    int b = idx / (Dm*NCH);
    const float* base = gvf + ((size_t)b*Lsz + c*CHL)*D3;
    float a = 1.f, h = 0.f;
    for (int l = 0; l < CHL; l++) {
        const float* r = base + (size_t)l*D3;
        float v = r[Dm + d], f = r[2*Dm + d];
        float ft = 1.f / (1.f + __expf(1.f - f));
        h = ft*h + (1.f - ft)*v;
        a *= ft;
    }
    ca[idx] = a;
    ch[idx] = h;
}

__global__ void scan2_k(const float* __restrict__ ca, float* __restrict__ ch)
{
    int idx = blockIdx.x*blockDim.x + threadIdx.x;
    if (idx >= Bsz*Dm) return;
    int d = idx % Dm, b = idx / Dm;
    float h = 0.f;
#pragma unroll
    for (int c = 0; c < NCH; c++) {
        size_t o = ((size_t)b*NCH + c)*Dm + d;
        float a = ca[o], hl = ch[o];
        ch[o] = h;                 // carry-in for chunk c
        h = a*h + hl;
    }
}

__global__ void scan3_k(const float* __restrict__ gvf, const float* __restrict__ ch,
                        float* __restrict__ out)
{
    int idx = blockIdx.x*blockDim.x + threadIdx.x;
    if (idx >= Bsz*NCH*Dm) return;
    int d = idx % Dm;
    int c = (idx / Dm) % NCH;
    int b = idx / (Dm*NCH);
    const float* base = gvf + ((size_t)b*Lsz + c*CHL)*D3;
    float h = ch[idx];
    for (int l = 0; l < CHL; l++) {
        const float* r = base + (size_t)l*D3;
        float g = r[d], v = r[Dm + d], f = r[2*Dm + d];
        float ft = 1.f / (1.f + __expf(1.f - f));
        h = ft*h + (1.f - ft)*v;
        float gs = 1.f / (1.f + __expf(-g));
        out[((size_t)(b*Lsz + c*CHL + l))*Dm + d] = gs * h;
    }
}

// ---------------- silu(gate) * up (in place into gate) ----------------------
__global__ void silu_mul_k(float* __restrict__ g, const float* __restrict__ u, int n)
{
    int i = blockIdx.x*blockDim.x + threadIdx.x;
    if (i < n) {
        float x = g[i];
        g[i] = (x / (1.f + __expf(-x))) * u[i];
    }
}

// ---------------- host orchestration ----------------------------------------
static inline void run_gemm(const float* A, const float* B, const float* R,
                            float* C, int M, int N, int K, int addRes)
{
    dim3 grid((N + GBN - 1)/GBN, M/GBM);
    gemm_tc_k<<<grid, 256>>>(A, B, R, C, M, N, K, addRes);
}

extern "C" void kernel_launch(void* const* d_in, const int* in_sizes, int n_in,
                              void* d_out, int out_size)
{
    const int*   x         = (const int*)  d_in[0];
    const float* emb       = (const float*)d_in[1];
    const float* pos_emb   = (const float*)d_in[2];
    const float* attn_qkv  = (const float*)d_in[3];
    const float* attn_out  = (const float*)d_in[4];
    const float* attn_norm = (const float*)d_in[5];
    const float* rec_in    = (const float*)d_in[6];
    const float* rec_out   = (const float*)d_in[7];
    const float* rec_norm  = (const float*)d_in[8];
    const float* ffn_gate  = (const float*)d_in[9];
    const float* ffn_up    = (const float*)d_in[10];
    const float* ffn_down  = (const float*)d_in[11];
    const float* ffn_norm  = (const float*)d_in[12];
    const float* final_nrm = (const float*)d_in[13];
    float* out = (float*)d_out;

    float *ph, *pxn, *pa, *pb, *pt, *pkt, *pvt, *pca, *pch;
    cudaGetSymbolAddress((void**)&ph,  g_h);
    cudaGetSymbolAddress((void**)&pxn, g_xn);
    cudaGetSymbolAddress((void**)&pa,  g_a);
    cudaGetSymbolAddress((void**)&pb,  g_b);
    cudaGetSymbolAddress((void**)&pt,  g_t);
    cudaGetSymbolAddress((void**)&pkt, g_kt);
    cudaGetSymbolAddress((void**)&pvt, g_vt);
    cudaGetSymbolAddress((void**)&pca, g_ca);
    cudaGetSymbolAddress((void**)&pch, g_ch);

    const int rms_blocks = (TOK*32 + 255)/256;
    const int sc13_blocks = (Bsz*NCH*Dm + 255)/256;
    const int sc2_blocks  = (Bsz*Dm + 255)/256;

    embed_k<<<TOK, Dm>>>(x, emb, pos_emb, ph);

    int ai = 0, ri = 0;
    for (int i = 0; i < 14; i++) {
        bool is_attn = ((i + 1) % 3 == 0);
        if (is_attn) {
            rmsnorm_k<<<rms_blocks, 256>>>(ph, attn_norm + (size_t)ai*Dm, pxn);
            run_gemm(pxn, attn_qkv + (size_t)ai*D3*Dm, nullptr, pa, TOK, D3, Dm, 0);
            kvt_k<<<(Bsz*Hh*HD*Lsz + 255)/256, 256>>>(pa, pkt, pvt);
            attn_k<<<Bsz*Hh*64, 256>>>(pa, pkt, pvt, pt);
            run_gemm(pt, attn_out + (size_t)ai*Dm*Dm, ph, ph, TOK, Dm, Dm, 1);
            ai++;
        } else {
            rmsnorm_k<<<rms_blocks, 256>>>(ph, rec_norm + (size_t)ri*Dm, pxn);
            run_gemm(pxn, rec_in + (size_t)ri*D3*Dm, nullptr, pa, TOK, D3, Dm, 0);
            scan1_k<<<sc13_blocks, 256>>>(pa, pca, pch);
            scan2_k<<<sc2_blocks, 256>>>(pca, pch);
            scan3_k<<<sc13_blocks, 256>>>(pa, pch, pt);
            run_gemm(pt, rec_out + (size_t)ri*Dm*Dm, ph, ph, TOK, Dm, Dm, 1);
            ri++;
        }
        // FFN
        rmsnorm_k<<<rms_blocks, 256>>>(ph, ffn_norm + (size_t)i*Dm, pxn);
        run_gemm(pxn, ffn_gate + (size_t)i*D3*Dm, nullptr, pa, TOK, D3, Dm, 0);
        run_gemm(pxn, ffn_up   + (size_t)i*D3*Dm, nullptr, pb, TOK, D3, Dm, 0);
        silu_mul_k<<<(TOK*D3 + 255)/256, 256>>>(pa, pb, TOK*D3);
        run_gemm(pa, ffn_down + (size_t)i*Dm*D3, ph, ph, TOK, Dm, D3, 1);
    }

    rmsnorm_k<<<rms_blocks, 256>>>(ph, final_nrm, pxn);
    run_gemm(pxn, emb, nullptr, out, TOK, Vv, Dm, 0);
}

// round 5
// speedup vs baseline: 1.8181x; 1.0446x over previous
#include <cuda_runtime.h>
#include <cuda_bf16.h>
#include <mma.h>
#include <math.h>
#include <cstdint>

using namespace nvcuda;

#define Bsz 32
#define Lsz 512
#define Dm  288
#define D3  864
#define Hh  8
#define HD  36
#define Vv  4096
#define TOK (Bsz*Lsz)   // 16384

#define NCH 16
#define CHL (Lsz/NCH)   // 32

// weight buffer offsets (elements)
#define W_QKV  0
#define W_AOUT 995328
#define W_RIN  1327104
#define W_ROUT 3815424
#define W_GATE 4644864
#define W_UP   8128512
#define W_DOWN 11612160
#define W_EMB  15095808
#define W_TOT  16275456

// ---------------- scratch (device globals; no allocations allowed) ----------
__device__ float g_h [TOK*Dm];
__device__ float g_a [TOK*D3];
__device__ float g_b [TOK*D3];
__device__ float g_kt[Bsz*Hh*HD*Lsz];
__device__ float g_vt[Bsz*Hh*HD*Lsz];
__device__ float g_ca[Bsz*NCH*Dm];
__device__ float g_ch[Bsz*NCH*Dm];

__device__ __nv_bfloat16 g_wh [W_TOT];
__device__ __nv_bfloat16 g_wl [W_TOT];
__device__ __nv_bfloat16 g_xnh[TOK*Dm];
__device__ __nv_bfloat16 g_xnl[TOK*Dm];
__device__ __nv_bfloat16 g_ash[TOK*D3];
__device__ __nv_bfloat16 g_asl[TOK*D3];
__device__ __nv_bfloat16 g_th [TOK*Dm];
__device__ __nv_bfloat16 g_tl [TOK*Dm];

// ---------------- helpers ----------------------------------------------------
__device__ __forceinline__ void bf16split(float v, __nv_bfloat16* hi, __nv_bfloat16* lo)
{
    __nv_bfloat16 h = __float2bfloat16_rn(v);
    *hi = h;
    *lo = __float2bfloat16_rn(v - __bfloat162float(h));
}

// ---------------- weight split ------------------------------------------------
__global__ void wsplit_k(const float* __restrict__ src, __nv_bfloat16* __restrict__ hi,
                         __nv_bfloat16* __restrict__ lo, int n)
{
    int i = blockIdx.x*blockDim.x + threadIdx.x;
    if (i < n) bf16split(src[i], hi + i, lo + i);
}

// ---------------- embedding ---------------------------------------------------
__global__ void embed_k(const int* __restrict__ x, const float* __restrict__ emb,
                        const float* __restrict__ pos, float* __restrict__ h)
{
    int t = blockIdx.x;
    int d = threadIdx.x;
    int tok = x[t];
    int l = t & (Lsz-1);
    h[(size_t)t*Dm + d] = emb[(size_t)tok*Dm + d] + pos[(size_t)l*Dm + d];
}

// ---------------- rmsnorm (warp per token), bf16 hi/lo output -----------------
__global__ void rmsnorm_k(const float* __restrict__ x, const float* __restrict__ scale,
                          __nv_bfloat16* __restrict__ yh, __nv_bfloat16* __restrict__ yl)
{
    int gw   = (blockIdx.x*blockDim.x + threadIdx.x) >> 5;
    int lane = threadIdx.x & 31;
    if (gw >= TOK) return;
    const float* xr = x + (size_t)gw*Dm;
    float v[9];
    float ss = 0.f;
#pragma unroll
    for (int j = 0; j < 9; j++) { v[j] = xr[lane + 32*j]; ss += v[j]*v[j]; }
#pragma unroll
    for (int off = 16; off; off >>= 1) ss += __shfl_xor_sync(~0u, ss, off);
    float norm = sqrtf(ss * (1.f/Dm));
    float inv  = 1.f / (norm + 1e-6f);
#pragma unroll
    for (int j = 0; j < 9; j++) {
        float y = scale[lane + 32*j] * v[j] * inv;
        size_t o = (size_t)gw*Dm + lane + 32*j;
        bf16split(y, yh + o, yl + o);
    }
}

// ---------------- bf16x3 tensor-core GEMM, cp.async double buffered -----------
// C[M,N] = A[M,K]*B[N,K]^T (+R). A,B pre-split into hi/lo bf16 (K-contiguous).
// BM=128, BN=64, BK=32, 256 thr, 8 warps (4m x 2n), warp tile 32x32 (2x2 k16).
#define GBM 128
#define GBN 64
#define GBK 32
#define PIT 40                 // bf16 pitch (80B)
#define SA_PL (GBM*PIT)        // 5120 elems per A plane per stage
#define SB_PL (GBN*PIT)        // 2560 elems per B plane per stage
#define SMEM_BYTES ((4*SA_PL + 4*SB_PL)*2)   // 61440

__device__ __forceinline__ void cp16(void* dst, const void* src, int sz)
{
    unsigned int d = (unsigned int)__cvta_generic_to_shared(dst);
    asm volatile("cp.async.cg.shared.global [%0], [%1], 16, %2;" :: "r"(d), "l"(src), "r"(sz));
}

__global__ void gemm_tc_k(const __nv_bfloat16* __restrict__ Ahg, const __nv_bfloat16* __restrict__ Alg,
                          const __nv_bfloat16* __restrict__ Bhg, const __nv_bfloat16* __restrict__ Blg,
                          const float* __restrict__ R, float* __restrict__ C,
                          int M, int N, int K, int addRes)
{
    extern __shared__ __align__(16) __nv_bfloat16 sm[];
    __nv_bfloat16* sAh = sm;
    __nv_bfloat16* sAl = sm + 2*SA_PL;
    __nv_bfloat16* sBh = sm + 4*SA_PL;
    __nv_bfloat16* sBl = sm + 4*SA_PL + 2*SB_PL;

    int tid = threadIdx.x;
    int wid = tid >> 5;
    int wm  = wid & 3;
    int wn  = wid >> 2;
    int m0  = blockIdx.y*GBM;
    int n0  = blockIdx.x*GBN;

    int arow = tid >> 2;            // 0..63 (two iters -> 128)
    int ak8  = (tid & 3) << 3;
    int brow = tid >> 2;            // 0..63
    int bok  = (n0 + brow) < N;
    size_t boff = (size_t)(bok ? (n0 + brow) : 0)*K + ak8;
    int bsz = bok ? 16 : 0;

#define LOAD_STAGE(st, k0)                                                        \
    do {                                                                          \
        _Pragma("unroll")                                                         \
        for (int t = 0; t < 2; t++) {                                             \
            int row = arow + t*64;                                                \
            size_t go = (size_t)(m0+row)*K + (k0) + ak8;                          \
            cp16(sAh + (st)*SA_PL + row*PIT + ak8, Ahg + go, 16);                 \
            cp16(sAl + (st)*SA_PL + row*PIT + ak8, Alg + go, 16);                 \
        }                                                                         \
        cp16(sBh + (st)*SB_PL + brow*PIT + ak8, Bhg + boff + (k0), bsz);          \
        cp16(sBl + (st)*SB_PL + brow*PIT + ak8, Blg + boff + (k0), bsz);          \
        asm volatile("cp.async.commit_group;");                                   \
    } while (0)

    wmma::fragment<wmma::accumulator,16,16,16,float> acc[2][2];
#pragma unroll
    for (int i = 0; i < 2; i++)
#pragma unroll
        for (int j = 0; j < 2; j++)
            wmma::fill_fragment(acc[i][j], 0.f);

    LOAD_STAGE(0, 0);
    int stage = 0;
    for (int k0 = 0; k0 < K; k0 += GBK) {
        if (k0 + GBK < K) {
            LOAD_STAGE(stage^1, k0 + GBK);
            asm volatile("cp.async.wait_group 1;");
        } else {
            asm volatile("cp.async.wait_group 0;");
        }
        __syncthreads();

        const __nv_bfloat16* pAh = sAh + stage*SA_PL;
        const __nv_bfloat16* pAl = sAl + stage*SA_PL;
        const __nv_bfloat16* pBh = sBh + stage*SB_PL;
        const __nv_bfloat16* pBl = sBl + stage*SB_PL;
#pragma unroll
        for (int kk = 0; kk < GBK; kk += 16) {
            wmma::fragment<wmma::matrix_a,16,16,16,__nv_bfloat16,wmma::row_major> ah[2], al[2];
            wmma::fragment<wmma::matrix_b,16,16,16,__nv_bfloat16,wmma::col_major> bh[2], bl[2];
#pragma unroll
            for (int i = 0; i < 2; i++) {
                wmma::load_matrix_sync(ah[i], pAh + (wm*32 + i*16)*PIT + kk, PIT);
                wmma::load_matrix_sync(al[i], pAl + (wm*32 + i*16)*PIT + kk, PIT);
            }
#pragma unroll
            for (int j = 0; j < 2; j++) {
                wmma::load_matrix_sync(bh[j], pBh + (wn*32 + j*16)*PIT + kk, PIT);
                wmma::load_matrix_sync(bl[j], pBl + (wn*32 + j*16)*PIT + kk, PIT);
            }
#pragma unroll
            for (int i = 0; i < 2; i++)
#pragma unroll
                for (int j = 0; j < 2; j++) {
                    wmma::mma_sync(acc[i][j], ah[i], bh[j], acc[i][j]);
                    wmma::mma_sync(acc[i][j], ah[i], bl[j], acc[i][j]);
                    wmma::mma_sync(acc[i][j], al[i], bh[j], acc[i][j]);
                }
        }
        stage ^= 1;
        __syncthreads();
    }

#pragma unroll
    for (int i = 0; i < 2; i++) {
#pragma unroll
        for (int j = 0; j < 2; j++) {
            int nb = n0 + wn*32 + j*16;
            if (nb >= N) continue;
            size_t off = (size_t)(m0 + wm*32 + i*16)*N + nb;
            if (addRes) {
                wmma::fragment<wmma::accumulator,16,16,16,float> rf;
                wmma::load_matrix_sync(rf, R + off, N, wmma::mem_row_major);
#pragma unroll
                for (int e = 0; e < rf.num_elements; e++)
                    acc[i][j].x[e] += rf.x[e];
            }
            wmma::store_matrix_sync(C + off, acc[i][j], N, wmma::mem_row_major);
        }
    }
#undef LOAD_STAGE
}

// ---------------- K/V transpose to [bh][d][l] ----------------------------------
__global__ void kvt_k(const float* __restrict__ qkv, float* __restrict__ kt,
                      float* __restrict__ vt)
{
    int idx = blockIdx.x*blockDim.x + threadIdx.x;
    if (idx >= Bsz*Hh*HD*Lsz) return;
    int d  = idx % HD;
    int l  = (idx / HD) & (Lsz-1);
    int bh = idx / (HD*Lsz);
    int b = bh >> 3, h = bh & 7;
    size_t src = (size_t)(b*Lsz + l)*D3 + h*HD + d;
    size_t dst = ((size_t)bh*HD + d)*Lsz + l;
    kt[dst] = qkv[src + Dm];
    vt[dst] = qkv[src + 2*Dm];
}

// ---------------- attention: warp per (b,h,q), online softmax, split output ---
__global__ void attn_k(const float* __restrict__ qkv, const float* __restrict__ kt,
                       const float* __restrict__ vt,
                       __nv_bfloat16* __restrict__ oh, __nv_bfloat16* __restrict__ ol)
{
    int wid  = threadIdx.x >> 5;
    int lane = threadIdx.x & 31;
    int bh = blockIdx.x >> 6;
    int q  = ((blockIdx.x & 63) << 3) + wid;
    int b = bh >> 3, h = bh & 7;

    const float* qrow = qkv + (size_t)(b*Lsz + q)*D3 + h*HD;
    float qv[HD];
#pragma unroll
    for (int d = 0; d < HD; d++) qv[d] = qrow[d] * (1.f/6.f);

    const float* ktb = kt + (size_t)bh*HD*Lsz;
    const float* vtb = vt + (size_t)bh*HD*Lsz;

    float m = -1e30f, ssum = 0.f;
    float o[HD];
#pragma unroll
    for (int d = 0; d < HD; d++) o[d] = 0.f;

    int nch = (q >> 5) + 1;
    for (int c = 0; c < nch; c++) {
        int k = (c << 5) + lane;
        float s = -1e30f;
        if (k <= q) {
            float acc = 0.f;
#pragma unroll
            for (int d = 0; d < HD; d++) acc += qv[d] * ktb[d*Lsz + k];
            s = acc;
        }
        float cm = s;
#pragma unroll
        for (int off = 16; off; off >>= 1) cm = fmaxf(cm, __shfl_xor_sync(~0u, cm, off));
        float nm = fmaxf(m, cm);
        float alpha = __expf(m - nm);
        float p = (k <= q) ? __expf(s - nm) : 0.f;
        float ps = p;
#pragma unroll
        for (int off = 16; off; off >>= 1) ps += __shfl_xor_sync(~0u, ps, off);
        ssum = ssum*alpha + ps;
#pragma unroll
        for (int d = 0; d < HD; d++) o[d] = o[d]*alpha + p * vtb[d*Lsz + k];
        m = nm;
    }
#pragma unroll
    for (int d = 0; d < HD; d++) {
#pragma unroll
        for (int off = 16; off; off >>= 1) o[d] += __shfl_xor_sync(~0u, o[d], off);
    }
    if (lane == 0) {
        float inv = 1.f/ssum;
        size_t base = (size_t)(b*Lsz + q)*Dm + h*HD;
#pragma unroll
        for (int d = 0; d < HD; d++)
            bf16split(o[d]*inv, oh + base + d, ol + base + d);
    }
}

// ---------------- parallel linear recurrence scan (3 passes) -------------------
__global__ void scan1_k(const float* __restrict__ gvf,
                        float* __restrict__ ca, float* __restrict__ ch)
{
    int idx = blockIdx.x*blockDim.x + threadIdx.x;
    if (idx >= Bsz*NCH*Dm) return;
    int d = idx % Dm;
    int c = (idx / Dm) % NCH;
    int b = idx / (Dm*NCH);
    const float* base = gvf + ((size_t)b*Lsz + c*CHL)*D3;
    float a = 1.f, h = 0.f;
    for (int l = 0; l < CHL; l++) {
        const float* r = base + (size_t)l*D3;
        float v = r[Dm + d], f = r[2*Dm + d];
        float ft = 1.f / (1.f + __expf(1.f - f));
        h = ft*h + (1.f - ft)*v;
        a *= ft;
    }
    ca[idx] = a;
    ch[idx] = h;
}

__global__ void scan2_k(const float* __restrict__ ca, float* __restrict__ ch)
{
    int idx = blockIdx.x*blockDim.x + threadIdx.x;
    if (idx >= Bsz*Dm) return;
    int d = idx % Dm, b = idx / Dm;
    float h = 0.f;
#pragma unroll
    for (int c = 0; c < NCH; c++) {
        size_t o = ((size_t)b*NCH + c)*Dm + d;
        float a = ca[o], hl = ch[o];
        ch[o] = h;
        h = a*h + hl;
    }
}

__global__ void scan3_k(const float* __restrict__ gvf, const float* __restrict__ ch,
                        __nv_bfloat16* __restrict__ oh, __nv_bfloat16* __restrict__ ol)
{
    int idx = blockIdx.x*blockDim.x + threadIdx.x;
    if (idx >= Bsz*NCH*Dm) return;
    int d = idx % Dm;
    int c = (idx / Dm) % NCH;
    int b = idx / (Dm*NCH);
    const float* base = gvf + ((size_t)b*Lsz + c*CHL)*D3;
    float h = ch[idx];
    for (int l = 0; l < CHL; l++) {
        const float* r = base + (size_t)l*D3;
        float g = r[d], v = r[Dm + d], f = r[2*Dm + d];
        float ft = 1.f / (1.f + __expf(1.f - f));
        h = ft*h + (1.f - ft)*v;
        float gs = 1.f / (1.f + __expf(-g));
        size_t o = ((size_t)(b*Lsz + c*CHL + l))*Dm + d;
        bf16split(gs*h, oh + o, ol + o);
    }
}

// ---------------- silu(gate)*up -> split bf16 ---------------------------------
__global__ void silu_mul_k(const float* __restrict__ g, const float* __restrict__ u,
                           __nv_bfloat16* __restrict__ oh, __nv_bfloat16* __restrict__ ol, int n)
{
    int i = blockIdx.x*blockDim.x + threadIdx.x;
    if (i < n) {
        float x = g[i];
        float v = (x / (1.f + __expf(-x))) * u[i];
        bf16split(v, oh + i, ol + i);
    }
}

// ---------------- host orchestration ------------------------------------------
static inline void run_gemm(const __nv_bfloat16* Ah, const __nv_bfloat16* Al,
                            const __nv_bfloat16* wh, const __nv_bfloat16* wl, size_t woff,
                            const float* R, float* C, int M, int N, int K, int addRes)
{
    dim3 grid((N + GBN - 1)/GBN, M/GBM);
    gemm_tc_k<<<grid, 256, SMEM_BYTES>>>(Ah, Al, wh + woff, wl + woff, R, C, M, N, K, addRes);
}

extern "C" void kernel_launch(void* const* d_in, const int* in_sizes, int n_in,
                              void* d_out, int out_size)
{
    const int*   x         = (const int*)  d_in[0];
    const float* emb       = (const float*)d_in[1];
    const float* pos_emb   = (const float*)d_in[2];
    const float* attn_qkv  = (const float*)d_in[3];
    const float* attn_out  = (const float*)d_in[4];
    const float* attn_norm = (const float*)d_in[5];
    const float* rec_in    = (const float*)d_in[6];
    const float* rec_out   = (const float*)d_in[7];
    const float* rec_norm  = (const float*)d_in[8];
    const float* ffn_gate  = (const float*)d_in[9];
    const float* ffn_up    = (const float*)d_in[10];
    const float* ffn_down  = (const float*)d_in[11];
    const float* ffn_norm  = (const float*)d_in[12];
    const float* final_nrm = (const float*)d_in[13];
    float* out = (float*)d_out;

    static int smem_set = 0;
    if (!smem_set) {
        cudaFuncSetAttribute(gemm_tc_k, cudaFuncAttributeMaxDynamicSharedMemorySize, SMEM_BYTES);
        smem_set = 1;
    }

    float *ph, *pa, *pb, *pkt, *pvt, *pca, *pch;
    __nv_bfloat16 *pwh, *pwl, *pxnh, *pxnl, *pash, *pasl, *pth, *ptl;
    cudaGetSymbolAddress((void**)&ph,  g_h);
    cudaGetSymbolAddress((void**)&pa,  g_a);
    cudaGetSymbolAddress((void**)&pb,  g_b);
    cudaGetSymbolAddress((void**)&pkt, g_kt);
    cudaGetSymbolAddress((void**)&pvt, g_vt);
    cudaGetSymbolAddress((void**)&pca, g_ca);
    cudaGetSymbolAddress((void**)&pch, g_ch);
    cudaGetSymbolAddress((void**)&pwh, g_wh);
    cudaGetSymbolAddress((void**)&pwl, g_wl);
    cudaGetSymbolAddress((void**)&pxnh, g_xnh);
    cudaGetSymbolAddress((void**)&pxnl, g_xnl);
    cudaGetSymbolAddress((void**)&pash, g_ash);
    cudaGetSymbolAddress((void**)&pasl, g_asl);
    cudaGetSymbolAddress((void**)&pth, g_th);
    cudaGetSymbolAddress((void**)&ptl, g_tl);

    // weight pre-split (every call; ~30us)
    struct { const float* src; size_t off; int n; } ws[8] = {
        {attn_qkv, W_QKV,  4*D3*Dm}, {attn_out, W_AOUT, 4*Dm*Dm},
        {rec_in,   W_RIN, 10*D3*Dm}, {rec_out,  W_ROUT,10*Dm*Dm},
        {ffn_gate, W_GATE,14*D3*Dm}, {ffn_up,   W_UP,  14*D3*Dm},
        {ffn_down, W_DOWN,14*Dm*D3}, {emb,      W_EMB,  Vv*Dm},
    };
    for (int i = 0; i < 8; i++)
        wsplit_k<<<(ws[i].n + 255)/256, 256>>>(ws[i].src, pwh + ws[i].off, pwl + ws[i].off, ws[i].n);

    const int rms_blocks  = (TOK*32 + 255)/256;
    const int sc13_blocks = (Bsz*NCH*Dm + 255)/256;
    const int sc2_blocks  = (Bsz*Dm + 255)/256;

    embed_k<<<TOK, Dm>>>(x, emb, pos_emb, ph);

    int ai = 0, ri = 0;
    for (int i = 0; i < 14; i++) {
        bool is_attn = ((i + 1) % 3 == 0);
        if (is_attn) {
            rmsnorm_k<<<rms_blocks, 256>>>(ph, attn_norm + (size_t)ai*Dm, pxnh, pxnl);
            run_gemm(pxnh, pxnl, pwh, pwl, W_QKV + (size_t)ai*D3*Dm, nullptr, pa, TOK, D3, Dm, 0);
            kvt_k<<<(Bsz*Hh*HD*Lsz + 255)/256, 256>>>(pa, pkt, pvt);
            attn_k<<<Bsz*Hh*64, 256>>>(pa, pkt, pvt, pth, ptl);
            run_gemm(pth, ptl, pwh, pwl, W_AOUT + (size_t)ai*Dm*Dm, ph, ph, TOK, Dm, Dm, 1);
            ai++;
        } else {
            rmsnorm_k<<<rms_blocks, 256>>>(ph, rec_norm + (size_t)ri*Dm, pxnh, pxnl);
            run_gemm(pxnh, pxnl, pwh, pwl, W_RIN + (size_t)ri*D3*Dm, nullptr, pa, TOK, D3, Dm, 0);
            scan1_k<<<sc13_blocks, 256>>>(pa, pca, pch);
            scan2_k<<<sc2_blocks, 256>>>(pca, pch);
            scan3_k<<<sc13_blocks, 256>>>(pa, pch, pth, ptl);
            run_gemm(pth, ptl, pwh, pwl, W_ROUT + (size_t)ri*Dm*Dm, ph, ph, TOK, Dm, Dm, 1);
            ri++;
        }
        // FFN
        rmsnorm_k<<<rms_blocks, 256>>>(ph, ffn_norm + (size_t)i*Dm, pxnh, pxnl);
        run_gemm(pxnh, pxnl, pwh, pwl, W_GATE + (size_t)i*D3*Dm, nullptr, pa, TOK, D3, Dm, 0);
        run_gemm(pxnh, pxnl, pwh, pwl, W_UP   + (size_t)i*D3*Dm, nullptr, pb, TOK, D3, Dm, 0);
        silu_mul_k<<<(TOK*D3 + 255)/256, 256>>>(pa, pb, pash, pasl, TOK*D3);
        run_gemm(pash, pasl, pwh, pwl, W_DOWN + (size_t)i*Dm*D3, ph, ph, TOK, Dm, D3, 1);
    }

    rmsnorm_k<<<rms_blocks, 256>>>(ph, final_nrm, pxnh, pxnl);
    run_gemm(pxnh, pxnl, pwh, pwl, W_EMB, nullptr, out, TOK, Vv, Dm, 0);
}